// round 13
// baseline (speedup 1.0000x reference)
#include <cuda_runtime.h>
#include <cuda_fp16.h>
#include <cuda_bf16.h>
#include <cuda_pipeline_primitives.h>

#define IN_FEATURES  16384
#define OUT_FEATURES 16384
#define NNZ          1000000
#define BATCH        256
#define SLOTS        128          // bin capacity per row (Poisson(61); P(overflow)~1e-8)

// ---------------- device scratch (no runtime allocation allowed) ------------
__device__ __half g_xTh[(size_t)IN_FEATURES * BATCH];            // 8MB fp16 xT [IN,B]
__device__ int    g_count[OUT_FEATURES];                          // per-row edge count
__device__ int2   g_pairs[(size_t)OUT_FEATURES * SLOTS];          // 16MB binned edges

// ---------------- K1: binned scatter (4 edges/thread, single pass) -----------
__global__ void k_scatter(const int4* __restrict__ rows4,
                          const int4* __restrict__ cols4,
                          const float4* __restrict__ vals4) {
    int e = blockIdx.x * blockDim.x + threadIdx.x;
    if (e < NNZ / 4) {
        int4 r = rows4[e];
        int4 c = cols4[e];
        float4 v = vals4[e];
        int p0 = atomicAdd(&g_count[r.x], 1);
        g_pairs[((size_t)r.x << 7) + p0] = make_int2(c.x, __float_as_int(v.x));
        int p1 = atomicAdd(&g_count[r.y], 1);
        g_pairs[((size_t)r.y << 7) + p1] = make_int2(c.y, __float_as_int(v.y));
        int p2 = atomicAdd(&g_count[r.z], 1);
        g_pairs[((size_t)r.z << 7) + p2] = make_int2(c.z, __float_as_int(v.z));
        int p3 = atomicAdd(&g_count[r.w], 1);
        g_pairs[((size_t)r.w << 7) + p3] = make_int2(c.w, __float_as_int(v.w));
    }
}

// ---------------- K2: transpose x [B, IN] fp32 -> xTh [IN, B] fp16 -----------
__global__ __launch_bounds__(256) void k_transpose_x(const float* __restrict__ x) {
    __shared__ float tile[32][33];
    int tx = threadIdx.x;            // col within tile
    int ty = threadIdx.y;            // 0..7
    int col0 = blockIdx.x * 32;
    int b0   = blockIdx.y * 32;
#pragma unroll
    for (int j = 0; j < 4; j++)
        tile[ty + 8 * j][tx] = x[(size_t)(b0 + ty + 8 * j) * IN_FEATURES + col0 + tx];
    __syncthreads();
    int t = ty * 32 + tx;            // 0..255
    __half2* xT2 = (__half2*)g_xTh;
#pragma unroll
    for (int p = 0; p < 2; p++) {
        int cl = (t >> 4) + 16 * p;  // 0..31 (col within tile)
        int k  = t & 15;             // half2 index (2 batch vals)
        float lo = tile[2 * k][cl];
        float hi = tile[2 * k + 1][cl];
        xT2[(size_t)(col0 + cl) * (BATCH / 2) + (b0 / 2) + k] = __floats2half2_rn(lo, hi);
    }
}

// ---------------- K3: main — cp.async double-buffered bins, 8-deep LDG.128 ---
#define TPB   128          // 4 warps; each warp owns 4 rows, 32 lanes x int4
#define RPB   16           // rows per block (4 per warp)
#define RPW   4

// accumulate one edge's int4 (8 fp16 lanes) into A[0..7]
#define FMA8(P, V, A) {                                               \
    float2 _f;                                                        \
    _f = __half22float2(*(__half2*)&(P).x);                           \
    A[0] = fmaf(_f.x, (V), A[0]);  A[1] = fmaf(_f.y, (V), A[1]);      \
    _f = __half22float2(*(__half2*)&(P).y);                           \
    A[2] = fmaf(_f.x, (V), A[2]);  A[3] = fmaf(_f.y, (V), A[3]);      \
    _f = __half22float2(*(__half2*)&(P).z);                           \
    A[4] = fmaf(_f.x, (V), A[4]);  A[5] = fmaf(_f.y, (V), A[5]);      \
    _f = __half22float2(*(__half2*)&(P).w);                           \
    A[6] = fmaf(_f.x, (V), A[6]);  A[7] = fmaf(_f.y, (V), A[7]); }

__global__ __launch_bounds__(TPB) void k_main(float* __restrict__ out,
                                              const float* __restrict__ bias) {
    __shared__ int2  s_pairs[4][2][SLOTS];  // per-warp double-buffered bins, 8KB
    __shared__ float s_res[RPB][BATCH];     // 16KB staging
    const int4* __restrict__ xTv = (const int4*)g_xTh;   // 8 halves per elem

    int rbase = blockIdx.x * RPB;
    int warp  = threadIdx.x >> 5;
    int lane  = threadIdx.x & 31;
    int r0    = rbase + warp * RPW;

    // prefetch all 4 row counts (contiguous, 16B-aligned)
    int4 cnt4 = *(const int4*)&g_count[r0];
    int cnts[RPW] = {cnt4.x, cnt4.y, cnt4.z, cnt4.w};

    // stage row 0's bin into buffer 0 (register-free async copies)
    {
        const int4* pairs4 = (const int4*)(g_pairs + ((size_t)r0 << 7));
        int4* sp4 = (int4*)s_pairs[warp][0];
        __pipeline_memcpy_async(&sp4[lane],      &pairs4[lane],      16);
        __pipeline_memcpy_async(&sp4[lane + 32], &pairs4[lane + 32], 16);
        __pipeline_commit();
    }

#pragma unroll 1
    for (int rw = 0; rw < RPW; rw++) {
        int buf = rw & 1;
        if (rw + 1 < RPW) {
            // kick off next row's bin staging into the other buffer
            const int4* pairs4n = (const int4*)(g_pairs + ((size_t)(r0 + rw + 1) << 7));
            int4* sp4 = (int4*)s_pairs[warp][buf ^ 1];
            __pipeline_memcpy_async(&sp4[lane],      &pairs4n[lane],      16);
            __pipeline_memcpy_async(&sp4[lane + 32], &pairs4n[lane + 32], 16);
            __pipeline_commit();
            __pipeline_wait_prior(1);    // current buffer's group complete
        } else {
            __pipeline_wait_prior(0);
        }
        __syncwarp();

        const int2* sp = s_pairs[warp][buf];
        int n = cnts[rw];
        float a[8];
#pragma unroll
        for (int q = 0; q < 8; q++) a[q] = 0.f;

        int i = 0;
#pragma unroll 1
        for (; i + 8 <= n; i += 8) {
            int2 q0 = sp[i];     int2 q1 = sp[i + 1];
            int2 q2 = sp[i + 2]; int2 q3 = sp[i + 3];
            int2 q4 = sp[i + 4]; int2 q5 = sp[i + 5];
            int2 q6 = sp[i + 6]; int2 q7 = sp[i + 7];
            int4 x0 = xTv[q0.x * 32 + lane];
            int4 x1 = xTv[q1.x * 32 + lane];
            int4 x2 = xTv[q2.x * 32 + lane];
            int4 x3 = xTv[q3.x * 32 + lane];
            int4 x4 = xTv[q4.x * 32 + lane];
            int4 x5 = xTv[q5.x * 32 + lane];
            int4 x6 = xTv[q6.x * 32 + lane];
            int4 x7 = xTv[q7.x * 32 + lane];
            FMA8(x0, __int_as_float(q0.y), a);
            FMA8(x1, __int_as_float(q1.y), a);
            FMA8(x2, __int_as_float(q2.y), a);
            FMA8(x3, __int_as_float(q3.y), a);
            FMA8(x4, __int_as_float(q4.y), a);
            FMA8(x5, __int_as_float(q5.y), a);
            FMA8(x6, __int_as_float(q6.y), a);
            FMA8(x7, __int_as_float(q7.y), a);
        }
#pragma unroll 1
        for (; i < n; i++) {
            int2 q = sp[i];
            int4 xv = xTv[q.x * 32 + lane];
            FMA8(xv, __int_as_float(q.y), a);
        }
        __syncwarp();

        float bb = __ldg(&bias[r0 + rw]);
        int jr = warp * RPW + rw;
        float4 rr0 = make_float4(a[0] + bb, a[1] + bb, a[2] + bb, a[3] + bb);
        float4 rr1 = make_float4(a[4] + bb, a[5] + bb, a[6] + bb, a[7] + bb);
        *(float4*)&s_res[jr][8 * lane]     = rr0;
        *(float4*)&s_res[jr][8 * lane + 4] = rr1;
    }
    __syncthreads();

    // out[b, rbase..rbase+15]: 64B contiguous per batch lane
#pragma unroll
    for (int rep = 0; rep < 2; rep++) {
        int b = threadIdx.x + rep * TPB;
        float v[RPB];
#pragma unroll
        for (int rj = 0; rj < RPB; rj++) v[rj] = s_res[rj][b];
        float4* dst = (float4*)(out + (size_t)b * OUT_FEATURES + rbase);
#pragma unroll
        for (int q = 0; q < 4; q++)
            dst[q] = make_float4(v[4 * q], v[4 * q + 1], v[4 * q + 2], v[4 * q + 3]);
    }
}

// ---------------- launch ------------------------------------------------------
extern "C" void kernel_launch(void* const* d_in, const int* in_sizes, int n_in,
                              void* d_out, int out_size) {
    const float* x     = (const float*)d_in[0];
    const float* wvals = (const float*)d_in[1];
    const float* bias  = (const float*)d_in[2];
    const int*   rows  = (const int*)d_in[3];
    const int*   cols  = (const int*)d_in[4];
    float* out = (float*)d_out;

    // fork: transpose_x runs concurrently with memset+scatter
    cudaStream_t s2;
    cudaStreamCreateWithFlags(&s2, cudaStreamNonBlocking);
    cudaEvent_t e_fork, e_join;
    cudaEventCreateWithFlags(&e_fork, cudaEventDisableTiming);
    cudaEventCreateWithFlags(&e_join, cudaEventDisableTiming);

    cudaEventRecord(e_fork, 0);
    cudaStreamWaitEvent(s2, e_fork, 0);
    dim3 tgrid(IN_FEATURES / 32, BATCH / 32);
    dim3 tblk(32, 8);
    k_transpose_x<<<tgrid, tblk, 0, s2>>>(x);
    cudaEventRecord(e_join, s2);

    // main chain: zero counters -> binned scatter
    void* count_ptr = nullptr;
    cudaGetSymbolAddress(&count_ptr, g_count);
    cudaMemsetAsync(count_ptr, 0, OUT_FEATURES * sizeof(int));
    k_scatter<<<(NNZ / 4 + 255) / 256, 256>>>((const int4*)rows,
                                              (const int4*)cols,
                                              (const float4*)wvals);

    cudaStreamWaitEvent(0, e_join, 0);
    k_main<<<OUT_FEATURES / RPB, TPB>>>(out, bias);

    cudaEventDestroy(e_fork);
    cudaEventDestroy(e_join);
    cudaStreamDestroy(s2);
}

// round 14
// speedup vs baseline: 1.0102x; 1.0102x over previous
#include <cuda_runtime.h>
#include <cuda_fp16.h>
#include <cuda_bf16.h>

#define IN_FEATURES  16384
#define OUT_FEATURES 16384
#define NNZ          1000000
#define BATCH        256
#define SLOTS        128          // bin capacity per row (Poisson(61); P(overflow)~1e-8)

// ---------------- device scratch (no runtime allocation allowed) ------------
__device__ __half g_xTh[(size_t)IN_FEATURES * BATCH];            // 8MB fp16 xT [IN,B]
__device__ int    g_count[OUT_FEATURES];                          // per-row edge count
__device__ int2   g_pairs[(size_t)OUT_FEATURES * SLOTS];          // 16MB binned edges
__device__ int    g_work;                                         // work-steal cursor

// ---------------- K1: binned scatter (4 edges/thread, single pass) -----------
__global__ void k_scatter(const int4* __restrict__ rows4,
                          const int4* __restrict__ cols4,
                          const float4* __restrict__ vals4) {
    int e = blockIdx.x * blockDim.x + threadIdx.x;
    if (e < NNZ / 4) {
        int4 r = rows4[e];
        int4 c = cols4[e];
        float4 v = vals4[e];
        int p0 = atomicAdd(&g_count[r.x], 1);
        g_pairs[((size_t)r.x << 7) + p0] = make_int2(c.x, __float_as_int(v.x));
        int p1 = atomicAdd(&g_count[r.y], 1);
        g_pairs[((size_t)r.y << 7) + p1] = make_int2(c.y, __float_as_int(v.y));
        int p2 = atomicAdd(&g_count[r.z], 1);
        g_pairs[((size_t)r.z << 7) + p2] = make_int2(c.z, __float_as_int(v.z));
        int p3 = atomicAdd(&g_count[r.w], 1);
        g_pairs[((size_t)r.w << 7) + p3] = make_int2(c.w, __float_as_int(v.w));
    }
}

// ---------------- K2: transpose x [B, IN] fp32 -> xTh [IN, B] fp16 -----------
__global__ __launch_bounds__(256) void k_transpose_x(const float* __restrict__ x) {
    if (blockIdx.x == 0 && blockIdx.y == 0 && threadIdx.x == 0 && threadIdx.y == 0)
        g_work = 0;                  // reset steal cursor (ordered before k_main via join)
    __shared__ float tile[32][33];
    int tx = threadIdx.x;            // col within tile
    int ty = threadIdx.y;            // 0..7
    int col0 = blockIdx.x * 32;
    int b0   = blockIdx.y * 32;
#pragma unroll
    for (int j = 0; j < 4; j++)
        tile[ty + 8 * j][tx] = x[(size_t)(b0 + ty + 8 * j) * IN_FEATURES + col0 + tx];
    __syncthreads();
    int t = ty * 32 + tx;            // 0..255
    __half2* xT2 = (__half2*)g_xTh;
#pragma unroll
    for (int p = 0; p < 2; p++) {
        int cl = (t >> 4) + 16 * p;  // 0..31 (col within tile)
        int k  = t & 15;             // half2 index (2 batch vals)
        float lo = tile[2 * k][cl];
        float hi = tile[2 * k + 1][cl];
        xT2[(size_t)(col0 + cl) * (BATCH / 2) + (b0 / 2) + k] = __floats2half2_rn(lo, hi);
    }
}

// ---------------- K3: main — persistent work-stealing, R12 hot loop ----------
#define TPB   128          // 4 warps; each warp owns 4 rows, 32 lanes x int4
#define RPB   16           // rows per work item (4 per warp)
#define RPW   4
#define NWORK (OUT_FEATURES / RPB)   // 1024 work items

// accumulate one edge's int4 (8 fp16 lanes) into A[0..7]
#define FMA8(P, V, A) {                                               \
    float2 _f;                                                        \
    _f = __half22float2(*(__half2*)&(P).x);                           \
    A[0] = fmaf(_f.x, (V), A[0]);  A[1] = fmaf(_f.y, (V), A[1]);      \
    _f = __half22float2(*(__half2*)&(P).y);                           \
    A[2] = fmaf(_f.x, (V), A[2]);  A[3] = fmaf(_f.y, (V), A[3]);      \
    _f = __half22float2(*(__half2*)&(P).z);                           \
    A[4] = fmaf(_f.x, (V), A[4]);  A[5] = fmaf(_f.y, (V), A[5]);      \
    _f = __half22float2(*(__half2*)&(P).w);                           \
    A[6] = fmaf(_f.x, (V), A[6]);  A[7] = fmaf(_f.y, (V), A[7]); }

__global__ __launch_bounds__(TPB) void k_main(float* __restrict__ out,
                                              const float* __restrict__ bias) {
    __shared__ int2  s_pairs[4][SLOTS];     // per-warp whole-bin staging, 4KB
    __shared__ float s_res[RPB][BATCH];     // 16KB staging
    __shared__ int   s_widx;
    const int4* __restrict__ xTv = (const int4*)g_xTh;   // 8 halves per elem

    int warp  = threadIdx.x >> 5;
    int lane  = threadIdx.x & 31;
    int2* sp  = s_pairs[warp];

    while (true) {
        if (threadIdx.x == 0) s_widx = atomicAdd(&g_work, 1);
        __syncthreads();                      // also protects s_res reuse
        int widx = s_widx;
        if (widx >= NWORK) break;
        int rbase = widx * RPB;

#pragma unroll 1
        for (int rw = 0; rw < RPW; rw++) {
            int r = rbase + warp * RPW + rw;
            int n = g_count[r];

            // stage the whole bin (128 pairs = 64 int4) in 2 coalesced LDG.128
            {
                const int4* pairs4 = (const int4*)(g_pairs + ((size_t)r << 7));
                int4* sp4 = (int4*)sp;
                sp4[lane]      = pairs4[lane];
                sp4[lane + 32] = pairs4[lane + 32];
            }
            __syncwarp();

            float a[8];
#pragma unroll
            for (int q = 0; q < 8; q++) a[q] = 0.f;

            int i = 0;
#pragma unroll 1
            for (; i + 8 <= n; i += 8) {
                int2 q0 = sp[i];     int2 q1 = sp[i + 1];
                int2 q2 = sp[i + 2]; int2 q3 = sp[i + 3];
                int2 q4 = sp[i + 4]; int2 q5 = sp[i + 5];
                int2 q6 = sp[i + 6]; int2 q7 = sp[i + 7];
                int4 x0 = xTv[q0.x * 32 + lane];
                int4 x1 = xTv[q1.x * 32 + lane];
                int4 x2 = xTv[q2.x * 32 + lane];
                int4 x3 = xTv[q3.x * 32 + lane];
                int4 x4 = xTv[q4.x * 32 + lane];
                int4 x5 = xTv[q5.x * 32 + lane];
                int4 x6 = xTv[q6.x * 32 + lane];
                int4 x7 = xTv[q7.x * 32 + lane];
                FMA8(x0, __int_as_float(q0.y), a);
                FMA8(x1, __int_as_float(q1.y), a);
                FMA8(x2, __int_as_float(q2.y), a);
                FMA8(x3, __int_as_float(q3.y), a);
                FMA8(x4, __int_as_float(q4.y), a);
                FMA8(x5, __int_as_float(q5.y), a);
                FMA8(x6, __int_as_float(q6.y), a);
                FMA8(x7, __int_as_float(q7.y), a);
            }
#pragma unroll 1
            for (; i < n; i++) {
                int2 q = sp[i];
                int4 xv = xTv[q.x * 32 + lane];
                FMA8(xv, __int_as_float(q.y), a);
            }
            __syncwarp();

            float bb = __ldg(&bias[r]);
            int jr = warp * RPW + rw;
            float4 r0 = make_float4(a[0] + bb, a[1] + bb, a[2] + bb, a[3] + bb);
            float4 r1 = make_float4(a[4] + bb, a[5] + bb, a[6] + bb, a[7] + bb);
            *(float4*)&s_res[jr][8 * lane]     = r0;
            *(float4*)&s_res[jr][8 * lane + 4] = r1;
        }
        __syncthreads();

        // out[b, rbase..rbase+15]: 64B contiguous per batch lane
#pragma unroll
        for (int rep = 0; rep < 2; rep++) {
            int b = threadIdx.x + rep * TPB;
            float v[RPB];
#pragma unroll
            for (int rj = 0; rj < RPB; rj++) v[rj] = s_res[rj][b];
            float4* dst = (float4*)(out + (size_t)b * OUT_FEATURES + rbase);
#pragma unroll
            for (int q = 0; q < 4; q++)
                dst[q] = make_float4(v[4 * q], v[4 * q + 1], v[4 * q + 2], v[4 * q + 3]);
        }
    }
}

// ---------------- launch ------------------------------------------------------
extern "C" void kernel_launch(void* const* d_in, const int* in_sizes, int n_in,
                              void* d_out, int out_size) {
    const float* x     = (const float*)d_in[0];
    const float* wvals = (const float*)d_in[1];
    const float* bias  = (const float*)d_in[2];
    const int*   rows  = (const int*)d_in[3];
    const int*   cols  = (const int*)d_in[4];
    float* out = (float*)d_out;

    // fork: transpose_x (also resets g_work) concurrently with memset+scatter
    cudaStream_t s2;
    cudaStreamCreateWithFlags(&s2, cudaStreamNonBlocking);
    cudaEvent_t e_fork, e_join;
    cudaEventCreateWithFlags(&e_fork, cudaEventDisableTiming);
    cudaEventCreateWithFlags(&e_join, cudaEventDisableTiming);

    cudaEventRecord(e_fork, 0);
    cudaStreamWaitEvent(s2, e_fork, 0);
    dim3 tgrid(IN_FEATURES / 32, BATCH / 32);
    dim3 tblk(32, 8);
    k_transpose_x<<<tgrid, tblk, 0, s2>>>(x);
    cudaEventRecord(e_join, s2);

    // main chain: zero counters -> binned scatter
    void* count_ptr = nullptr;
    cudaGetSymbolAddress(&count_ptr, g_count);
    cudaMemsetAsync(count_ptr, 0, OUT_FEATURES * sizeof(int));
    k_scatter<<<(NNZ / 4 + 255) / 256, 256>>>((const int4*)rows,
                                              (const int4*)cols,
                                              (const float4*)wvals);

    cudaStreamWaitEvent(0, e_join, 0);

    // persistent grid sized to exact residency (host-side queries; capture-safe)
    int dev = 0, sms = 148, maxb = 6;
    cudaGetDevice(&dev);
    cudaDeviceGetAttribute(&sms, cudaDevAttrMultiProcessorCount, dev);
    cudaOccupancyMaxActiveBlocksPerMultiprocessor(&maxb, k_main, TPB, 0);
    int grid = sms * maxb;
    if (grid > NWORK) grid = NWORK;
    k_main<<<grid, TPB>>>(out, bias);

    cudaEventDestroy(e_fork);
    cudaEventDestroy(e_join);
    cudaStreamDestroy(s2);
}

// round 15
// speedup vs baseline: 1.0187x; 1.0085x over previous
#include <cuda_runtime.h>
#include <cuda_fp16.h>
#include <cuda_bf16.h>

#define IN_FEATURES  16384
#define OUT_FEATURES 16384
#define NNZ          1000000
#define BATCH        256
#define SLOTS        128          // bin capacity per row (Poisson(61); P(overflow)~1e-8)

// ---------------- device scratch (no runtime allocation allowed) ------------
__device__ __half g_xTh[(size_t)IN_FEATURES * BATCH];            // 8MB fp16 xT [IN,B]
__device__ int    g_count[OUT_FEATURES];                          // per-row edge count
__device__ int2   g_pairs[(size_t)OUT_FEATURES * SLOTS];          // 16MB binned edges

// ---------------- K1: binned scatter (4 edges/thread, single pass) -----------
__global__ void k_scatter(const int4* __restrict__ rows4,
                          const int4* __restrict__ cols4,
                          const float4* __restrict__ vals4) {
    int e = blockIdx.x * blockDim.x + threadIdx.x;
    if (e < NNZ / 4) {
        int4 r = rows4[e];
        int4 c = cols4[e];
        float4 v = vals4[e];
        int p0 = atomicAdd(&g_count[r.x], 1);
        g_pairs[((size_t)r.x << 7) + p0] = make_int2(c.x, __float_as_int(v.x));
        int p1 = atomicAdd(&g_count[r.y], 1);
        g_pairs[((size_t)r.y << 7) + p1] = make_int2(c.y, __float_as_int(v.y));
        int p2 = atomicAdd(&g_count[r.z], 1);
        g_pairs[((size_t)r.z << 7) + p2] = make_int2(c.z, __float_as_int(v.z));
        int p3 = atomicAdd(&g_count[r.w], 1);
        g_pairs[((size_t)r.w << 7) + p3] = make_int2(c.w, __float_as_int(v.w));
    }
}

// ---------------- K2: transpose x [B, IN] fp32 -> xTh [IN, B] fp16 -----------
__global__ __launch_bounds__(256) void k_transpose_x(const float* __restrict__ x) {
    __shared__ float tile[32][33];
    int tx = threadIdx.x;            // col within tile
    int ty = threadIdx.y;            // 0..7
    int col0 = blockIdx.x * 32;
    int b0   = blockIdx.y * 32;
#pragma unroll
    for (int j = 0; j < 4; j++)
        tile[ty + 8 * j][tx] = x[(size_t)(b0 + ty + 8 * j) * IN_FEATURES + col0 + tx];
    __syncthreads();
    int t = ty * 32 + tx;            // 0..255
    __half2* xT2 = (__half2*)g_xTh;
#pragma unroll
    for (int p = 0; p < 2; p++) {
        int cl = (t >> 4) + 16 * p;  // 0..31 (col within tile)
        int k  = t & 15;             // half2 index (2 batch vals)
        float lo = tile[2 * k][cl];
        float hi = tile[2 * k + 1][cl];
        xT2[(size_t)(col0 + cl) * (BATCH / 2) + (b0 / 2) + k] = __floats2half2_rn(lo, hi);
    }
}

// ---------------- K3: main — whole-bin staging, 8-deep LDG.128 pipeline ------
#define TPB   128          // 4 warps; each warp owns 4 rows, 32 lanes x int4
#define RPB   16           // rows per block (4 per warp)
#define RPW   4

// accumulate one edge's int4 (8 fp16 lanes) into A[0..7]
#define FMA8(P, V, A) {                                               \
    float2 _f;                                                        \
    _f = __half22float2(*(__half2*)&(P).x);                           \
    A[0] = fmaf(_f.x, (V), A[0]);  A[1] = fmaf(_f.y, (V), A[1]);      \
    _f = __half22float2(*(__half2*)&(P).y);                           \
    A[2] = fmaf(_f.x, (V), A[2]);  A[3] = fmaf(_f.y, (V), A[3]);      \
    _f = __half22float2(*(__half2*)&(P).z);                           \
    A[4] = fmaf(_f.x, (V), A[4]);  A[5] = fmaf(_f.y, (V), A[5]);      \
    _f = __half22float2(*(__half2*)&(P).w);                           \
    A[6] = fmaf(_f.x, (V), A[6]);  A[7] = fmaf(_f.y, (V), A[7]); }

__global__ __launch_bounds__(TPB) void k_main(float* __restrict__ out,
                                              const float* __restrict__ bias) {
    __shared__ int2  s_pairs[4][SLOTS];     // per-warp whole-bin staging, 4KB
    __shared__ float s_res[RPB][BATCH];     // 16KB staging
    const int4* __restrict__ xTv = (const int4*)g_xTh;   // 8 halves per elem

    int rbase = blockIdx.x * RPB;
    int warp  = threadIdx.x >> 5;
    int lane  = threadIdx.x & 31;
    int2* sp  = s_pairs[warp];

#pragma unroll 1
    for (int rw = 0; rw < RPW; rw++) {
        int r = rbase + warp * RPW + rw;
        int n = g_count[r];

        // stage the whole bin (128 pairs = 64 int4) in 2 coalesced LDG.128
        {
            const int4* pairs4 = (const int4*)(g_pairs + ((size_t)r << 7));
            int4* sp4 = (int4*)sp;
            sp4[lane]      = pairs4[lane];
            sp4[lane + 32] = pairs4[lane + 32];
        }
        __syncwarp();

        float a[8];
#pragma unroll
        for (int q = 0; q < 8; q++) a[q] = 0.f;

        int i = 0;
#pragma unroll 1
        for (; i + 8 <= n; i += 8) {
            int2 q0 = sp[i];     int2 q1 = sp[i + 1];
            int2 q2 = sp[i + 2]; int2 q3 = sp[i + 3];
            int2 q4 = sp[i + 4]; int2 q5 = sp[i + 5];
            int2 q6 = sp[i + 6]; int2 q7 = sp[i + 7];
            int4 x0 = xTv[q0.x * 32 + lane];
            int4 x1 = xTv[q1.x * 32 + lane];
            int4 x2 = xTv[q2.x * 32 + lane];
            int4 x3 = xTv[q3.x * 32 + lane];
            int4 x4 = xTv[q4.x * 32 + lane];
            int4 x5 = xTv[q5.x * 32 + lane];
            int4 x6 = xTv[q6.x * 32 + lane];
            int4 x7 = xTv[q7.x * 32 + lane];
            FMA8(x0, __int_as_float(q0.y), a);
            FMA8(x1, __int_as_float(q1.y), a);
            FMA8(x2, __int_as_float(q2.y), a);
            FMA8(x3, __int_as_float(q3.y), a);
            FMA8(x4, __int_as_float(q4.y), a);
            FMA8(x5, __int_as_float(q5.y), a);
            FMA8(x6, __int_as_float(q6.y), a);
            FMA8(x7, __int_as_float(q7.y), a);
        }
#pragma unroll 1
        for (; i < n; i++) {
            int2 q = sp[i];
            int4 xv = xTv[q.x * 32 + lane];
            FMA8(xv, __int_as_float(q.y), a);
        }
        __syncwarp();

        float bb = __ldg(&bias[r]);
        int jr = warp * RPW + rw;
        float4 r0 = make_float4(a[0] + bb, a[1] + bb, a[2] + bb, a[3] + bb);
        float4 r1 = make_float4(a[4] + bb, a[5] + bb, a[6] + bb, a[7] + bb);
        *(float4*)&s_res[jr][8 * lane]     = r0;
        *(float4*)&s_res[jr][8 * lane + 4] = r1;
    }
    __syncthreads();

    // out[b, rbase..rbase+15]: 64B contiguous per batch lane
#pragma unroll
    for (int rep = 0; rep < 2; rep++) {
        int b = threadIdx.x + rep * TPB;
        float v[RPB];
#pragma unroll
        for (int rj = 0; rj < RPB; rj++) v[rj] = s_res[rj][b];
        float4* dst = (float4*)(out + (size_t)b * OUT_FEATURES + rbase);
#pragma unroll
        for (int q = 0; q < 4; q++)
            dst[q] = make_float4(v[4 * q], v[4 * q + 1], v[4 * q + 2], v[4 * q + 3]);
    }
}

// ---------------- launch ------------------------------------------------------
extern "C" void kernel_launch(void* const* d_in, const int* in_sizes, int n_in,
                              void* d_out, int out_size) {
    const float* x     = (const float*)d_in[0];
    const float* wvals = (const float*)d_in[1];
    const float* bias  = (const float*)d_in[2];
    const int*   rows  = (const int*)d_in[3];
    const int*   cols  = (const int*)d_in[4];
    float* out = (float*)d_out;

    // fork: transpose_x runs concurrently with memset+scatter
    cudaStream_t s2;
    cudaStreamCreateWithFlags(&s2, cudaStreamNonBlocking);
    cudaEvent_t e_fork, e_join;
    cudaEventCreateWithFlags(&e_fork, cudaEventDisableTiming);
    cudaEventCreateWithFlags(&e_join, cudaEventDisableTiming);

    cudaEventRecord(e_fork, 0);
    cudaStreamWaitEvent(s2, e_fork, 0);
    dim3 tgrid(IN_FEATURES / 32, BATCH / 32);
    dim3 tblk(32, 8);
    k_transpose_x<<<tgrid, tblk, 0, s2>>>(x);
    cudaEventRecord(e_join, s2);

    // main chain: zero counters -> binned scatter
    void* count_ptr = nullptr;
    cudaGetSymbolAddress(&count_ptr, g_count);
    cudaMemsetAsync(count_ptr, 0, OUT_FEATURES * sizeof(int));
    k_scatter<<<(NNZ / 4 + 255) / 256, 256>>>((const int4*)rows,
                                              (const int4*)cols,
                                              (const float4*)wvals);

    cudaStreamWaitEvent(0, e_join, 0);
    k_main<<<OUT_FEATURES / RPB, TPB>>>(out, bias);

    cudaEventDestroy(e_fork);
    cudaEventDestroy(e_join);
    cudaStreamDestroy(s2);
}

// round 16
// speedup vs baseline: 1.0233x; 1.0045x over previous
#include <cuda_runtime.h>
#include <cuda_fp16.h>
#include <cuda_bf16.h>

#define IN_FEATURES  16384
#define OUT_FEATURES 16384
#define NNZ          1000000
#define BATCH        256
#define SLOTS        128          // bin capacity per row (Poisson(61); P(overflow)~1e-8)

// ---------------- device scratch (no runtime allocation allowed) ------------
__device__ __half g_xTh[(size_t)IN_FEATURES * BATCH];            // 8MB fp16 xT [IN,B]
__device__ int    g_count[OUT_FEATURES];                          // zero-init; k_main epilogue re-zeroes
__device__ int2   g_pairs[(size_t)OUT_FEATURES * SLOTS];          // 16MB binned edges

// ---------------- K1: binned scatter (4 edges/thread, single pass) -----------
__global__ void k_scatter(const int4* __restrict__ rows4,
                          const int4* __restrict__ cols4,
                          const float4* __restrict__ vals4) {
    int e = blockIdx.x * blockDim.x + threadIdx.x;
    if (e < NNZ / 4) {
        int4 r = rows4[e];
        int4 c = cols4[e];
        float4 v = vals4[e];
        int p0 = atomicAdd(&g_count[r.x], 1);
        g_pairs[((size_t)r.x << 7) + p0] = make_int2(c.x, __float_as_int(v.x));
        int p1 = atomicAdd(&g_count[r.y], 1);
        g_pairs[((size_t)r.y << 7) + p1] = make_int2(c.y, __float_as_int(v.y));
        int p2 = atomicAdd(&g_count[r.z], 1);
        g_pairs[((size_t)r.z << 7) + p2] = make_int2(c.z, __float_as_int(v.z));
        int p3 = atomicAdd(&g_count[r.w], 1);
        g_pairs[((size_t)r.w << 7) + p3] = make_int2(c.w, __float_as_int(v.w));
    }
}

// ---------------- K2: transpose x [B, IN] fp32 -> xTh [IN, B] fp16 -----------
__global__ __launch_bounds__(256) void k_transpose_x(const float* __restrict__ x) {
    __shared__ float tile[32][33];
    int tx = threadIdx.x;            // col within tile
    int ty = threadIdx.y;            // 0..7
    int col0 = blockIdx.x * 32;
    int b0   = blockIdx.y * 32;
#pragma unroll
    for (int j = 0; j < 4; j++)
        tile[ty + 8 * j][tx] = x[(size_t)(b0 + ty + 8 * j) * IN_FEATURES + col0 + tx];
    __syncthreads();
    int t = ty * 32 + tx;            // 0..255
    __half2* xT2 = (__half2*)g_xTh;
#pragma unroll
    for (int p = 0; p < 2; p++) {
        int cl = (t >> 4) + 16 * p;  // 0..31 (col within tile)
        int k  = t & 15;             // half2 index (2 batch vals)
        float lo = tile[2 * k][cl];
        float hi = tile[2 * k + 1][cl];
        xT2[(size_t)(col0 + cl) * (BATCH / 2) + (b0 / 2) + k] = __floats2half2_rn(lo, hi);
    }
}

// ---------------- K3: main — whole-bin staging, 8-deep LDG.128 pipeline ------
#define TPB   128          // 4 warps; each warp owns 4 rows, 32 lanes x int4
#define RPB   16           // rows per block (4 per warp)
#define RPW   4

// accumulate one edge's int4 (8 fp16 lanes) into A[0..7]
#define FMA8(P, V, A) {                                               \
    float2 _f;                                                        \
    _f = __half22float2(*(__half2*)&(P).x);                           \
    A[0] = fmaf(_f.x, (V), A[0]);  A[1] = fmaf(_f.y, (V), A[1]);      \
    _f = __half22float2(*(__half2*)&(P).y);                           \
    A[2] = fmaf(_f.x, (V), A[2]);  A[3] = fmaf(_f.y, (V), A[3]);      \
    _f = __half22float2(*(__half2*)&(P).z);                           \
    A[4] = fmaf(_f.x, (V), A[4]);  A[5] = fmaf(_f.y, (V), A[5]);      \
    _f = __half22float2(*(__half2*)&(P).w);                           \
    A[6] = fmaf(_f.x, (V), A[6]);  A[7] = fmaf(_f.y, (V), A[7]); }

__global__ __launch_bounds__(TPB) void k_main(float* __restrict__ out,
                                              const float* __restrict__ bias) {
    __shared__ int2  s_pairs[4][SLOTS];     // per-warp whole-bin staging, 4KB
    __shared__ float s_res[RPB][BATCH];     // 16KB staging
    const int4* __restrict__ xTv = (const int4*)g_xTh;   // 8 halves per elem

    int rbase = blockIdx.x * RPB;
    int warp  = threadIdx.x >> 5;
    int lane  = threadIdx.x & 31;
    int2* sp  = s_pairs[warp];

#pragma unroll 1
    for (int rw = 0; rw < RPW; rw++) {
        int r = rbase + warp * RPW + rw;
        int n = g_count[r];

        // stage the whole bin (128 pairs = 64 int4) in 2 coalesced LDG.128
        {
            const int4* pairs4 = (const int4*)(g_pairs + ((size_t)r << 7));
            int4* sp4 = (int4*)sp;
            sp4[lane]      = pairs4[lane];
            sp4[lane + 32] = pairs4[lane + 32];
        }
        __syncwarp();

        float a[8];
#pragma unroll
        for (int q = 0; q < 8; q++) a[q] = 0.f;

        int i = 0;
#pragma unroll 1
        for (; i + 8 <= n; i += 8) {
            int2 q0 = sp[i];     int2 q1 = sp[i + 1];
            int2 q2 = sp[i + 2]; int2 q3 = sp[i + 3];
            int2 q4 = sp[i + 4]; int2 q5 = sp[i + 5];
            int2 q6 = sp[i + 6]; int2 q7 = sp[i + 7];
            int4 x0 = xTv[q0.x * 32 + lane];
            int4 x1 = xTv[q1.x * 32 + lane];
            int4 x2 = xTv[q2.x * 32 + lane];
            int4 x3 = xTv[q3.x * 32 + lane];
            int4 x4 = xTv[q4.x * 32 + lane];
            int4 x5 = xTv[q5.x * 32 + lane];
            int4 x6 = xTv[q6.x * 32 + lane];
            int4 x7 = xTv[q7.x * 32 + lane];
            FMA8(x0, __int_as_float(q0.y), a);
            FMA8(x1, __int_as_float(q1.y), a);
            FMA8(x2, __int_as_float(q2.y), a);
            FMA8(x3, __int_as_float(q3.y), a);
            FMA8(x4, __int_as_float(q4.y), a);
            FMA8(x5, __int_as_float(q5.y), a);
            FMA8(x6, __int_as_float(q6.y), a);
            FMA8(x7, __int_as_float(q7.y), a);
        }
#pragma unroll 1
        for (; i < n; i++) {
            int2 q = sp[i];
            int4 xv = xTv[q.x * 32 + lane];
            FMA8(xv, __int_as_float(q.y), a);
        }
        __syncwarp();

        float bb = __ldg(&bias[r]);
        int jr = warp * RPW + rw;
        float4 r0 = make_float4(a[0] + bb, a[1] + bb, a[2] + bb, a[3] + bb);
        float4 r1 = make_float4(a[4] + bb, a[5] + bb, a[6] + bb, a[7] + bb);
        *(float4*)&s_res[jr][8 * lane]     = r0;
        *(float4*)&s_res[jr][8 * lane + 4] = r1;
    }
    __syncthreads();

    // epilogue: re-zero this block's counters for the next replay (replaces memset)
    if (threadIdx.x < RPB) g_count[rbase + threadIdx.x] = 0;

    // out[b, rbase..rbase+15]: 64B contiguous per batch lane
#pragma unroll
    for (int rep = 0; rep < 2; rep++) {
        int b = threadIdx.x + rep * TPB;
        float v[RPB];
#pragma unroll
        for (int rj = 0; rj < RPB; rj++) v[rj] = s_res[rj][b];
        float4* dst = (float4*)(out + (size_t)b * OUT_FEATURES + rbase);
#pragma unroll
        for (int q = 0; q < 4; q++)
            dst[q] = make_float4(v[4 * q], v[4 * q + 1], v[4 * q + 2], v[4 * q + 3]);
    }
}

// ---------------- launch ------------------------------------------------------
extern "C" void kernel_launch(void* const* d_in, const int* in_sizes, int n_in,
                              void* d_out, int out_size) {
    const float* x     = (const float*)d_in[0];
    const float* wvals = (const float*)d_in[1];
    const float* bias  = (const float*)d_in[2];
    const int*   rows  = (const int*)d_in[3];
    const int*   cols  = (const int*)d_in[4];
    float* out = (float*)d_out;

    // fork: transpose_x runs concurrently with scatter
    cudaStream_t s2;
    cudaStreamCreateWithFlags(&s2, cudaStreamNonBlocking);
    cudaEvent_t e_fork, e_join;
    cudaEventCreateWithFlags(&e_fork, cudaEventDisableTiming);
    cudaEventCreateWithFlags(&e_join, cudaEventDisableTiming);

    cudaEventRecord(e_fork, 0);
    cudaStreamWaitEvent(s2, e_fork, 0);
    dim3 tgrid(IN_FEATURES / 32, BATCH / 32);
    dim3 tblk(32, 8);
    k_transpose_x<<<tgrid, tblk, 0, s2>>>(x);
    cudaEventRecord(e_join, s2);

    // main chain: binned scatter (g_count zeroed at init / by previous k_main)
    k_scatter<<<(NNZ / 4 + 255) / 256, 256>>>((const int4*)rows,
                                              (const int4*)cols,
                                              (const float4*)wvals);

    cudaStreamWaitEvent(0, e_join, 0);
    k_main<<<OUT_FEATURES / RPB, TPB>>>(out, bias);

    cudaEventDestroy(e_fork);
    cudaEventDestroy(e_join);
    cudaStreamDestroy(s2);
}